// round 11
// baseline (speedup 1.0000x reference)
#include <cuda_runtime.h>
#include <cuda_fp16.h>
#include <cstdint>
#include <cstddef>

// ----- problem constants -----
#define LSITES  784
#define CHI     128
#define BATCH   1024
#define NCLS    10
#define BC      16                // samples per CTA
#define NCTA    (BATCH / BC)      // 64
#define THREADS 256
#define AROW    136               // padded A row stride (halves), K=128
#define ABUF_HALVES (BC * AROW)   // 2176
#define ABUF_BYTES  (ABUF_HALVES * 2)
#define HROW    132               // classifier h row stride (floats)
#define SITE_U4 4096              // uint4 fragment entries per site (= 64 KB)

// fragment-packed fp16 weights: g_WB[site][(w*16+c)*32+lane] = the 4 b32
// B-fragment values lane `lane` of warp `w` needs for k-chunk c.
__device__ uint4 g_WB[(size_t)LSITES * SITE_U4];   // 51.4 MB static scratch

// ---------------------------------------------------------------------------
// Prepass: W fp32 [n][s][a][b] -> fragment-packed fp16 g_WB
// value(k, bcol) = W[n][k*128 + bcol], k = s*128+a  (k in 0..255)
// u0 = (k0+2tg, b0) ; u1 = (k0+8+2tg, b0) ; u2/u3 same with b1 = b0+8
// where k0 = c*16, b0 = w*16 + (lane>>2), tg = lane&3
// ---------------------------------------------------------------------------
__global__ void __launch_bounds__(256) prep_kernel(const float* __restrict__ W) {
    extern __shared__ __half sw[];   // [256][132] halves: sw[k*132 + b]
    const int n   = blockIdx.x;
    const int tid = threadIdx.x;
    const float* Wg = W + (size_t)n * (2 * CHI * CHI);

    for (int i = 0; i < 128; ++i) {
        int e = i * 256 + tid;            // e = k*128 + b
        int k = e >> 7;
        int b = e & 127;
        sw[k * 132 + b] = __float2half_rn(Wg[e]);
    }
    __syncthreads();

    for (int i = 0; i < 16; ++i) {
        int idx  = i * 256 + tid;         // (w*16 + c)*32 + lane
        int lane = idx & 31;
        int c    = (idx >> 5) & 15;
        int w    = idx >> 9;
        int tg   = lane & 3;
        int g    = lane >> 2;
        int k0   = c * 16;
        int b0   = w * 16 + g;
        int b1   = b0 + 8;

        uint4 v;
        {
            __half2 t;
            t = __halves2half2(sw[(k0 + 2*tg) * 132 + b0],     sw[(k0 + 2*tg + 1) * 132 + b0]);
            v.x = *reinterpret_cast<uint32_t*>(&t);
            t = __halves2half2(sw[(k0 + 8 + 2*tg) * 132 + b0], sw[(k0 + 9 + 2*tg) * 132 + b0]);
            v.y = *reinterpret_cast<uint32_t*>(&t);
            t = __halves2half2(sw[(k0 + 2*tg) * 132 + b1],     sw[(k0 + 2*tg + 1) * 132 + b1]);
            v.z = *reinterpret_cast<uint32_t*>(&t);
            t = __halves2half2(sw[(k0 + 8 + 2*tg) * 132 + b1], sw[(k0 + 9 + 2*tg) * 132 + b1]);
            v.w = *reinterpret_cast<uint32_t*>(&t);
        }
        g_WB[(size_t)n * SITE_U4 + idx] = v;
    }
}

// ---------------------------------------------------------------------------
#define MMA16816(AC, A0, A1, A2, A3, B0, B1)                                  \
    asm volatile(                                                             \
        "mma.sync.aligned.m16n8k16.row.col.f32.f16.f16.f32 "                  \
        "{%0,%1,%2,%3}, {%4,%5,%6,%7}, {%8,%9}, {%0,%1,%2,%3};\n"             \
        : "+f"((AC)[0]), "+f"((AC)[1]), "+f"((AC)[2]), "+f"((AC)[3])          \
        : "r"(A0), "r"(A1), "r"(A2), "r"(A3), "r"(B0), "r"(B1))

// One site: prefetch B/x for n+1 into BNXT, MMA with BCUR, fold, publish.
#define SITE_BODY(NN, P, BCUR, BNXT)                                          \
{                                                                             \
    const int n_ = (NN);                                                      \
    float nx00 = 0.f, nx01 = 0.f, nx10 = 0.f, nx11 = 0.f;                     \
    if (n_ + 1 < LSITES) {                                                    \
        const uint4* wp_ = wptr + (size_t)(n_ + 1) * SITE_U4;                 \
        _Pragma("unroll")                                                     \
        for (int c = 0; c < 16; ++c) {                                        \
            uint4 t_ = __ldg(wp_ + c * 32);                                   \
            BNXT[c][0] = t_.x; BNXT[c][1] = t_.y;                             \
            BNXT[c][2] = t_.z; BNXT[c][3] = t_.w;                             \
        }                                                                     \
        nx00 = __ldg(px00 + n_ + 1); nx01 = __ldg(px01 + n_ + 1);             \
        nx10 = __ldg(px10 + n_ + 1); nx11 = __ldg(px11 + n_ + 1);             \
    }                                                                         \
    float acc0[8], acc1[8];                                                   \
    _Pragma("unroll")                                                         \
    for (int i = 0; i < 8; ++i) { acc0[i] = 0.f; acc1[i] = 0.f; }             \
    {                                                                         \
        const uint32_t ab_ = a_base + (uint32_t)((P) * ABUF_BYTES);           \
        _Pragma("unroll")                                                     \
        for (int ca = 0; ca < 8; ++ca) {                                      \
            uint32_t a0, a1, a2, a3;                                          \
            asm volatile(                                                     \
                "ldmatrix.sync.aligned.m8n8.x4.shared.b16 {%0,%1,%2,%3}, [%4];\n" \
                : "=r"(a0), "=r"(a1), "=r"(a2), "=r"(a3)                      \
                : "r"(ab_ + (uint32_t)(ca * 32)));                            \
            MMA16816(acc0 + 0, a0, a1, a2, a3, BCUR[ca][0],     BCUR[ca][1]); \
            MMA16816(acc0 + 4, a0, a1, a2, a3, BCUR[ca][2],     BCUR[ca][3]); \
            MMA16816(acc1 + 0, a0, a1, a2, a3, BCUR[ca + 8][0], BCUR[ca + 8][1]); \
            MMA16816(acc1 + 4, a0, a1, a2, a3, BCUR[ca + 8][2], BCUR[ca + 8][3]); \
        }                                                                     \
    }                                                                         \
    h[0] += cx00 * acc0[0] + cx01 * acc1[0];                                  \
    h[1] += cx00 * acc0[1] + cx01 * acc1[1];                                  \
    h[2] += cx10 * acc0[2] + cx11 * acc1[2];                                  \
    h[3] += cx10 * acc0[3] + cx11 * acc1[3];                                  \
    h[4] += cx00 * acc0[4] + cx01 * acc1[4];                                  \
    h[5] += cx00 * acc0[5] + cx01 * acc1[5];                                  \
    h[6] += cx10 * acc0[6] + cx11 * acc1[6];                                  \
    h[7] += cx10 * acc0[7] + cx11 * acc1[7];                                  \
    cx00 = nx00; cx01 = nx01; cx10 = nx10; cx11 = nx11;                       \
    {                                                                         \
        __half* ad_ = Abuf[1 - (P)];                                          \
        *(__half2*)(ad_ + g * AROW + c0)           = __floats2half2_rn(h[0], h[1]); \
        *(__half2*)(ad_ + g * AROW + c0 + 8)       = __floats2half2_rn(h[4], h[5]); \
        *(__half2*)(ad_ + (g + 8) * AROW + c0)     = __floats2half2_rn(h[2], h[3]); \
        *(__half2*)(ad_ + (g + 8) * AROW + c0 + 8) = __floats2half2_rn(h[6], h[7]); \
    }                                                                         \
    __syncthreads();                                                          \
}

// ---------------------------------------------------------------------------
// Main kernel: 256 threads, register-resident h, B fragments streamed from
// global via coalesced LDG.128 (one site ahead). Smem holds only A (fp16 h).
// ---------------------------------------------------------------------------
__global__ void __launch_bounds__(THREADS, 1) mps_kernel(const float* __restrict__ x,
                                                         const float* __restrict__ V,
                                                         float* __restrict__ out) {
    __shared__ __half Abuf[2][ABUF_HALVES];   // fp16(h) double buffer
    __shared__ float  Fh[BC * HROW];          // classifier scratch

    const int tid  = threadIdx.x;
    const int cta  = blockIdx.x;
    const int w    = tid >> 5;               // warp 0..7 -> cols [w*16, w*16+16)
    const int lane = tid & 31;
    const int g    = lane >> 2;              // 0..7
    const int tg   = lane & 3;               // 0..3
    const int c0   = w * 16 + 2 * tg;        // owned h/delta column base

    // h register layout (matches acc fragments):
    //  h[0]=H[g][c0]   h[1]=H[g][c0+1]   h[2]=H[g+8][c0]   h[3]=H[g+8][c0+1]
    //  h[4]=H[g][c0+8] h[5]=H[g][c0+9]   h[6]=H[g+8][c0+8] h[7]=H[g+8][c0+9]
    float h[8];
#pragma unroll
    for (int i = 0; i < 8; ++i) h[i] = 1.0f;

    // init Abuf[0] = fp16(1)
    {
        const __half one = __float2half_rn(1.f);
        for (int i = tid; i < ABUF_HALVES; i += THREADS) Abuf[0][i] = one;
    }
    __syncthreads();

    // per-thread x streams: samples cta*16+g and cta*16+g+8, both features
    const int sg0 = cta * BC + g;
    const int sg1 = sg0 + 8;
    const float* px00 = x + ((size_t)sg0 * 2 + 0) * LSITES;
    const float* px01 = x + ((size_t)sg0 * 2 + 1) * LSITES;
    const float* px10 = x + ((size_t)sg1 * 2 + 0) * LSITES;
    const float* px11 = x + ((size_t)sg1 * 2 + 1) * LSITES;
    float cx00 = __ldg(px00), cx01 = __ldg(px01);
    float cx10 = __ldg(px10), cx11 = __ldg(px11);

    // A-ldmatrix lane address (within a buffer)
    const uint32_t abuf_s = (uint32_t)__cvta_generic_to_shared(&Abuf[0][0]);
    const uint32_t a_base = abuf_s + (uint32_t)((((lane & 15) * AROW) + ((lane >> 4) * 8)) * 2);

    // per-thread B fragment stream base
    const uint4* wptr = g_WB + (size_t)w * 512 + lane;

    // B fragment ping-pong registers
    uint32_t bP[16][4], bQ[16][4];
    // prologue: load site 0 into bP
#pragma unroll
    for (int c = 0; c < 16; ++c) {
        uint4 t = __ldg(wptr + c * 32);
        bP[c][0] = t.x; bP[c][1] = t.y; bP[c][2] = t.z; bP[c][3] = t.w;
    }

    for (int n = 0; n < LSITES; n += 2) {
        SITE_BODY(n,     0, bP, bQ);
        SITE_BODY(n + 1, 1, bQ, bP);
    }

    // dump h to smem for the classifier
    Fh[g * HROW + c0]           = h[0];
    Fh[g * HROW + c0 + 1]       = h[1];
    Fh[g * HROW + c0 + 8]       = h[4];
    Fh[g * HROW + c0 + 9]       = h[5];
    Fh[(g + 8) * HROW + c0]     = h[2];
    Fh[(g + 8) * HROW + c0 + 1] = h[3];
    Fh[(g + 8) * HROW + c0 + 8] = h[6];
    Fh[(g + 8) * HROW + c0 + 9] = h[7];
    __syncthreads();

    // classifier: logits = h @ V  (16 samples x 10 classes per CTA)
    if (tid < BC * NCLS) {
        int r = tid / NCLS, c = tid % NCLS;
        const float* hr = Fh + r * HROW;
        float s = 0.f;
#pragma unroll 8
        for (int a = 0; a < CHI; ++a) s += hr[a] * __ldg(V + a * NCLS + c);
        out[(size_t)(cta * BC + r) * NCLS + c] = s;
    }
}

// ---------------------------------------------------------------------------
extern "C" void kernel_launch(void* const* d_in, const int* in_sizes, int n_in,
                              void* d_out, int out_size) {
    const float* x = nullptr;  // 1024*2*784    = 1605632
    const float* W = nullptr;  // 784*2*128*128 = 25690112
    const float* V = nullptr;  // 128*10        = 1280
    for (int i = 0; i < n_in; ++i) {
        if (in_sizes[i] == BATCH * 2 * LSITES)            x = (const float*)d_in[i];
        else if (in_sizes[i] == LSITES * 2 * CHI * CHI)   W = (const float*)d_in[i];
        else if (in_sizes[i] == CHI * NCLS)               V = (const float*)d_in[i];
    }
    float* out = (float*)d_out;

    cudaFuncSetAttribute(prep_kernel, cudaFuncAttributeMaxDynamicSharedMemorySize, 256 * 132 * 2);

    prep_kernel<<<LSITES, 256, 256 * 132 * 2>>>(W);
    mps_kernel<<<NCTA, THREADS>>>(x, V, out);
    (void)out_size;
}